// round 2
// baseline (speedup 1.0000x reference)
#include <cuda_runtime.h>
#include <math.h>

#define B_    64
#define LQ_   20
#define LD_   512
#define D_    300

// ---------------- constants ----------------
__constant__ float c_mu[11] = {1.0f,0.9f,0.7f,0.5f,0.3f,0.1f,-0.1f,-0.3f,-0.5f,-0.7f,-0.9f};
// c2 = -0.5 / sigma^2
__constant__ float c_c2[11] = {-500000.0f,-50.f,-50.f,-50.f,-50.f,-50.f,-50.f,-50.f,-50.f,-50.f,-50.f};
__constant__ int c_poolQ[16] = {0,0,0,1,2,1,1,2,2,3,3,3,0,1,2,3};
__constant__ int c_poolD[16] = {0,2,1,0,0,1,2,1,2,0,1,2,3,3,3,3};
__constant__ int c_qbase[4]  = {0,20,39,57};
__constant__ int c_qlen[4]   = {20,19,18,5};
__constant__ int c_dlen[4]   = {512,511,510,10};

// ---------------- device scratch ----------------
// q vectors: rows 0..19 qu, 20..38 qb, 39..56 qt, 57..61 qs, 62..63 zero
__device__ float g_qall[(size_t)B_*64*128];
// d vectors: [b][dtype 0..3][pos<512][128]; 0=du(512),1=db(511),2=dt(510),3=ds(10)
__device__ float g_dall[(size_t)B_*4*512*128];
// gaussian accumulators: [b][dtype][qrow 64][11]
__device__ float g_acc[(size_t)B_*4*64*11];
__device__ float g_qbow[B_*128];
__device__ float g_dbow[B_*128];
// transposed weights: Wt[(kk*300+dd)*128 + o]
__device__ float g_WtU[300*128];
__device__ float g_WtB[600*128];
__device__ float g_WtT[900*128];
__device__ float g_WtD[1500*128];
__device__ float g_bowT[300*128];

// ---------------- weight transpose ----------------
__global__ void wtrans_kernel(const float* __restrict__ cu, const float* __restrict__ cb,
                              const float* __restrict__ ct, const float* __restrict__ cd,
                              const float* __restrict__ bw)
{
    int idx = blockIdx.x*blockDim.x + threadIdx.x;
    if (idx >= 1500*128) return;
    int o = idx & 127, kd = idx >> 7;
    g_WtD[idx] = cd[o*1500 + kd];
    if (kd < 300) { g_WtU[idx] = cu[o*300 + kd]; g_bowT[idx] = bw[o*300 + kd]; }
    if (kd < 600) { g_WtB[idx] = cb[o*600 + kd]; }
    if (kd < 900) { g_WtT[idx] = ct[o*900 + kd]; }
}

// ---------------- zero accumulators ----------------
__global__ void zero_kernel()
{
    int idx = blockIdx.x*blockDim.x + threadIdx.x;
    if (idx < B_*4*64*11) g_acc[idx] = 0.f;
}

// ---------------- bow: w_bow[b][o] = (sum_l emb[tok_l]) . bowW_o + L*bow_b[o] ----------------
__global__ void bow_kernel(const int* __restrict__ qwt, const int* __restrict__ dwt,
                           const float* __restrict__ emb, const float* __restrict__ bow_b)
{
    int b = blockIdx.x; int side = blockIdx.y;
    const int* tok = side ? (dwt + b*LD_) : (qwt + b*LQ_);
    int L = side ? LD_ : LQ_;
    __shared__ float sv[304];
    for (int idx = threadIdx.x; idx < 300; idx += blockDim.x) {
        float s = 0.f;
        #pragma unroll 4
        for (int l = 0; l < L; l++) s += emb[(size_t)tok[l]*300 + idx];
        sv[idx] = s;
    }
    __syncthreads();
    int t = threadIdx.x;
    if (t < 128) {
        float acc = (float)L * bow_b[t];
        #pragma unroll 4
        for (int dd = 0; dd < 300; dd++) acc = fmaf(sv[dd], g_bowT[dd*128 + t], acc);
        (side ? g_dbow : g_qbow)[b*128 + t] = acc;
    }
}

// ---------------- fused uni/bi/tri conv + relu + L2 norm ----------------
__device__ __forceinline__ void conv_store_type(float* acc, float bias, float* buf, float* ninv,
                                                float* outp, int p0, int pbase, int o, int Lvalid)
{
    #pragma unroll
    for (int p = 0; p < 16; p++) {
        acc[p] = fmaxf(acc[p] + bias, 0.f);
        buf[(pbase + p)*128 + o] = acc[p];
    }
    __syncthreads();
    int wid = threadIdx.x >> 5, lane = threadIdx.x & 31;
    #pragma unroll
    for (int r = 0; r < 4; r++) {
        int p = wid*4 + r;
        float s = 0.f;
        #pragma unroll
        for (int j = 0; j < 4; j++) { float v = buf[p*128 + lane + 32*j]; s = fmaf(v, v, s); }
        #pragma unroll
        for (int off = 16; off >= 1; off >>= 1) s += __shfl_xor_sync(0xffffffffu, s, off);
        if (lane == 0) ninv[p] = 1.f / fmaxf(sqrtf(s), 1e-10f);
    }
    __syncthreads();
    #pragma unroll
    for (int p = 0; p < 16; p++) {
        int pg = p0 + pbase + p;
        if (pg < Lvalid) outp[(size_t)pg*128 + o] = acc[p] * ninv[pbase + p];
    }
    __syncthreads();
}

__global__ void __launch_bounds__(256, 2) conv_kernel(
    const int* __restrict__ tok_all, int L, int side,
    const float* __restrict__ emb,
    const float* __restrict__ bU, const float* __restrict__ bB, const float* __restrict__ bT)
{
    __shared__ float A[34*300];             // 40800 B; reused as buf/ninv later
    float* buf  = A;                        // [32][128]
    float* ninv = A + 32*128;               // [32]

    int b = blockIdx.y, chunk = blockIdx.x;
    int p0 = chunk*32;
    const int* tok = tok_all + b*L;
    int nrows = L - p0; if (nrows > 34) nrows = 34;
    for (int idx = threadIdx.x; idx < 34*300; idx += 256) {
        int r = idx / 300;
        A[idx] = (r < nrows) ? emb[(size_t)tok[p0 + r]*300 + (idx - r*300)] : 0.f;
    }
    __syncthreads();

    int o = threadIdx.x & 127;
    int half = threadIdx.x >> 7;
    int pbase = half*16;
    float accU[16], accB[16], accT[16];
    #pragma unroll
    for (int p = 0; p < 16; p++) { accU[p]=0.f; accB[p]=0.f; accT[p]=0.f; }

    const float* Arow = A + pbase*300;
    for (int dd = 0; dd < 300; dd += 2) {
        float2 a2[18];
        #pragma unroll
        for (int j = 0; j < 18; j++) a2[j] = *(const float2*)(Arow + j*300 + dd);
        float wu0  = g_WtU[dd*128+o],         wu1  = g_WtU[(dd+1)*128+o];
        float wb00 = g_WtB[dd*128+o],         wb01 = g_WtB[(dd+1)*128+o];
        float wb10 = g_WtB[(300+dd)*128+o],   wb11 = g_WtB[(301+dd)*128+o];
        float wt00 = g_WtT[dd*128+o],         wt01 = g_WtT[(dd+1)*128+o];
        float wt10 = g_WtT[(300+dd)*128+o],   wt11 = g_WtT[(301+dd)*128+o];
        float wt20 = g_WtT[(600+dd)*128+o],   wt21 = g_WtT[(601+dd)*128+o];
        #pragma unroll
        for (int p = 0; p < 16; p++) {
            accU[p] = fmaf(a2[p].x,   wu0,  accU[p]);
            accU[p] = fmaf(a2[p].y,   wu1,  accU[p]);
            accB[p] = fmaf(a2[p].x,   wb00, accB[p]);
            accB[p] = fmaf(a2[p].y,   wb01, accB[p]);
            accB[p] = fmaf(a2[p+1].x, wb10, accB[p]);
            accB[p] = fmaf(a2[p+1].y, wb11, accB[p]);
            accT[p] = fmaf(a2[p].x,   wt00, accT[p]);
            accT[p] = fmaf(a2[p].y,   wt01, accT[p]);
            accT[p] = fmaf(a2[p+1].x, wt10, accT[p]);
            accT[p] = fmaf(a2[p+1].y, wt11, accT[p]);
            accT[p] = fmaf(a2[p+2].x, wt20, accT[p]);
            accT[p] = fmaf(a2[p+2].y, wt21, accT[p]);
        }
    }
    __syncthreads();   // last A read done; A reused as buf below

    float *oU, *oB, *oT; int Lu, Lb2, Lt2;
    if (side == 0) {
        float* qb_ = g_qall + (size_t)b*64*128;
        oU = qb_; oB = qb_ + 20*128; oT = qb_ + 39*128;
        Lu = 20; Lb2 = 19; Lt2 = 18;
    } else {
        float* dbp = g_dall + (size_t)b*4*512*128;
        oU = dbp; oB = dbp + (size_t)512*128; oT = dbp + (size_t)2*512*128;
        Lu = 512; Lb2 = 511; Lt2 = 510;
    }
    conv_store_type(accU, bU[o], buf, ninv, oU, p0, pbase, o, Lu);
    conv_store_type(accB, bB[o], buf, ninv, oB, p0, pbase, o, Lb2);
    conv_store_type(accT, bT[o], buf, ninv, oT, p0, pbase, o, Lt2);
}

// ---------------- entity branch: desc conv + attention + L2 ----------------
__global__ void __launch_bounds__(256, 2) entity_kernel(
    const int* __restrict__ ids_e, const int* __restrict__ ids_desc, const int* __restrict__ ids_car,
    const float* __restrict__ emb, const float* __restrict__ bD,
    const float* __restrict__ ent_emb, const float* __restrict__ car_emb,
    int NE, int side)
{
    __shared__ float A[20*300];
    __shared__ float econv[128];
    __shared__ float att[10];
    __shared__ float sc[10];
    __shared__ float part[8];
    __shared__ float wbs[128];
    __shared__ int   cid[10];
    __shared__ float sninv;

    int b = blockIdx.y, e = blockIdx.x;
    int t = threadIdx.x;
    const float* bow = side ? (g_dbow + b*128) : (g_qbow + b*128);
    const int* dtok = ids_desc + (b*NE + e)*20;
    for (int idx = t; idx < 20*300; idx += 256) {
        int r = idx / 300;
        A[idx] = emb[(size_t)dtok[r]*300 + (idx - r*300)];
    }
    if (t < 128) wbs[t] = bow[t];
    if (t < 10)  cid[t] = ids_car[(b*NE + e)*10 + t];
    __syncthreads();

    // desc conv (window 5, 16 positions, 128 filters), max over positions
    int o = t & 127, half = t >> 7;
    float acc[8];
    #pragma unroll
    for (int p = 0; p < 8; p++) acc[p] = 0.f;
    const float* Arow = A + half*8*300;
    for (int dd = 0; dd < 300; dd += 2) {
        float2 a2[12];
        #pragma unroll
        for (int j = 0; j < 12; j++) a2[j] = *(const float2*)(Arow + j*300 + dd);
        #pragma unroll
        for (int kk = 0; kk < 5; kk++) {
            float w0 = g_WtD[(kk*300 + dd)*128 + o];
            float w1 = g_WtD[(kk*300 + dd + 1)*128 + o];
            #pragma unroll
            for (int p = 0; p < 8; p++) {
                acc[p] = fmaf(a2[p + kk].x, w0, acc[p]);
                acc[p] = fmaf(a2[p + kk].y, w1, acc[p]);
            }
        }
    }
    float bias = bD[o];
    float m = 0.f;
    #pragma unroll
    for (int p = 0; p < 8; p++) m = fmaxf(m, fmaxf(acc[p] + bias, 0.f));
    if (half == 0) econv[o] = m;
    __syncthreads();
    if (half == 1) econv[o] = fmaxf(econv[o], m);
    __syncthreads();

    // attention scores: sc[c] = dot(w_bow, car_emb[cid[c]])
    for (int c = 0; c < 10; c++) {
        float v = (t < 128) ? wbs[t] * car_emb[(size_t)cid[c]*128 + t] : 0.f;
        #pragma unroll
        for (int off = 16; off >= 1; off >>= 1) v += __shfl_xor_sync(0xffffffffu, v, off);
        if ((t & 31) == 0) part[t >> 5] = v;
        __syncthreads();
        if (t == 0) sc[c] = part[0] + part[1] + part[2] + part[3];
        __syncthreads();
    }
    if (t == 0) {
        float mx = sc[0];
        #pragma unroll
        for (int c = 1; c < 10; c++) mx = fmaxf(mx, sc[c]);
        float s = 0.f;
        float ev[10];
        #pragma unroll
        for (int c = 0; c < 10; c++) { ev[c] = __expf(sc[c] - mx); s += ev[c]; }
        float inv = 1.f / s;
        #pragma unroll
        for (int c = 0; c < 10; c++) att[c] = ev[c] * inv;
    }
    __syncthreads();

    // combine + L2 norm
    float val = 0.f, v2 = 0.f;
    if (t < 128) {
        float ewt = 0.f;
        #pragma unroll
        for (int c = 0; c < 10; c++) ewt = fmaf(att[c], car_emb[(size_t)cid[c]*128 + t], ewt);
        int eid = ids_e[b*NE + e];
        val = ent_emb[(size_t)eid*128 + t] + econv[t] + ewt;
        v2 = val * val;
    }
    #pragma unroll
    for (int off = 16; off >= 1; off >>= 1) v2 += __shfl_xor_sync(0xffffffffu, v2, off);
    if ((t & 31) == 0) part[t >> 5] = v2;
    __syncthreads();
    if (t == 0) sninv = 1.f / fmaxf(sqrtf(part[0] + part[1] + part[2] + part[3]), 1e-10f);
    __syncthreads();
    if (t < 128) {
        float* outp = (side == 0)
            ? (g_qall + ((size_t)b*64 + 57 + e)*128)
            : (g_dall + (((size_t)b*4 + 3)*512 + e)*128);
        outp[t] = val * sninv;
    }
}

// ---------------- kernel pooling ----------------
__global__ void __launch_bounds__(256) pool_kernel(const float* __restrict__ dwm,
                                                   const float* __restrict__ dem)
{
    int b = blockIdx.z, dt = blockIdx.y, chunk = blockIdx.x;
    int Ld = c_dlen[dt];
    int d0 = chunk*64;
    if (d0 >= Ld) return;

    __shared__ float sQ[64*17];
    __shared__ float sD[64*17];
    __shared__ float sMd[64];

    int tid = threadIdx.x;
    if (tid < 64) {
        int dpos = d0 + tid;
        float m = 0.f;
        if (dpos < Ld) m = (dt < 3) ? dwm[b*512 + dpos] : dem[b*10 + dpos];
        sMd[tid] = m;
    }

    int ty = tid >> 4, tx = tid & 15;
    float sim[16];
    #pragma unroll
    for (int i = 0; i < 16; i++) sim[i] = 0.f;

    int qr = tid >> 2, c4 = (tid & 3) << 2;
    for (int kk = 0; kk < 128; kk += 16) {
        __syncthreads();
        float4 vq = *(const float4*)(g_qall + ((size_t)b*64 + qr)*128 + kk + c4);
        sQ[qr*17 + c4 + 0] = vq.x; sQ[qr*17 + c4 + 1] = vq.y;
        sQ[qr*17 + c4 + 2] = vq.z; sQ[qr*17 + c4 + 3] = vq.w;
        float4 vd = *(const float4*)(g_dall + (((size_t)b*4 + dt)*512 + d0 + qr)*128 + kk + c4);
        sD[qr*17 + c4 + 0] = vd.x; sD[qr*17 + c4 + 1] = vd.y;
        sD[qr*17 + c4 + 2] = vd.z; sD[qr*17 + c4 + 3] = vd.w;
        __syncthreads();
        #pragma unroll
        for (int kkl = 0; kkl < 16; kkl++) {
            float aq[4], ad[4];
            #pragma unroll
            for (int i = 0; i < 4; i++) aq[i] = sQ[(ty*4 + i)*17 + kkl];
            #pragma unroll
            for (int j = 0; j < 4; j++) ad[j] = sD[(tx*4 + j)*17 + kkl];
            #pragma unroll
            for (int i = 0; i < 4; i++)
                #pragma unroll
                for (int j = 0; j < 4; j++)
                    sim[i*4 + j] = fmaf(aq[i], ad[j], sim[i*4 + j]);
        }
    }

    float mdv[4];
    #pragma unroll
    for (int j = 0; j < 4; j++) mdv[j] = sMd[tx*4 + j];

    float acc[44];
    #pragma unroll
    for (int i = 0; i < 44; i++) acc[i] = 0.f;
    #pragma unroll
    for (int i = 0; i < 4; i++) {
        #pragma unroll
        for (int j = 0; j < 4; j++) {
            float s = sim[i*4 + j];
            float md = mdv[j];
            #pragma unroll
            for (int k = 0; k < 11; k++) {
                float tdev = s - c_mu[k];
                float e = __expf(c_c2[k] * tdev * tdev);
                acc[i*11 + k] = fmaf(e, md, acc[i*11 + k]);
            }
        }
    }

    #pragma unroll
    for (int off = 8; off >= 1; off >>= 1)
        #pragma unroll
        for (int i = 0; i < 44; i++)
            acc[i] += __shfl_xor_sync(0xffffffffu, acc[i], off);

    if (tx == 0) {
        #pragma unroll
        for (int i = 0; i < 4; i++) {
            int qrow = ty*4 + i;
            float* dst = g_acc + (((size_t)b*4 + dt)*64 + qrow)*11;
            #pragma unroll
            for (int k = 0; k < 11; k++) atomicAdd(&dst[k], acc[i*11 + k]);
        }
    }
}

// ---------------- finalize: log/mask/dense/tanh ----------------
__global__ void finalize_kernel(const float* __restrict__ qwm, const float* __restrict__ qem,
                                const float* __restrict__ dW, const float* __restrict__ dfb,
                                float* __restrict__ out)
{
    int b = blockIdx.x, t = threadIdx.x;
    __shared__ float red[256];
    float val = 0.f;
    if (t < 176) {
        int pool = t / 11, k = t - pool*11;
        int qt = c_poolQ[pool], dtp = c_poolD[pool];
        int base = c_qbase[qt], len = c_qlen[qt];
        float s = 0.f;
        for (int r = 0; r < len; r++) {
            float a = g_acc[(((size_t)b*4 + dtp)*64 + base + r)*11 + k];
            float mq = (qt < 3) ? qwm[b*20 + r] : qem[b*5 + r];
            s += logf(fmaxf(a, 1e-10f)) * 0.01f * mq;
        }
        val = s * dW[t];
    }
    red[t] = val;
    __syncthreads();
    for (int off = 128; off >= 1; off >>= 1) {
        if (t < off) red[t] += red[t + off];
        __syncthreads();
    }
    if (t == 0) out[b] = tanhf(red[0] + dfb[0]);
}

// ---------------- launch ----------------
extern "C" void kernel_launch(void* const* d_in, const int* in_sizes, int n_in,
                              void* d_out, int out_size)
{
    const int*   qwt = (const int*)  d_in[0];
    const float* qwm = (const float*)d_in[1];
    const int*   qei = (const int*)  d_in[2];
    const int*   qet = (const int*)  d_in[3];
    const int*   qew = (const int*)  d_in[4];
    const float* qem = (const float*)d_in[5];
    const int*   dwt = (const int*)  d_in[6];
    const float* dwm = (const float*)d_in[7];
    const int*   dei = (const int*)  d_in[8];
    const int*   det = (const int*)  d_in[9];
    const int*   dew = (const int*)  d_in[10];
    const float* dem = (const float*)d_in[11];
    const float* wrd = (const float*)d_in[12];
    const float* ent = (const float*)d_in[13];
    const float* car = (const float*)d_in[14];
    const float* bowW= (const float*)d_in[15];
    const float* bowb= (const float*)d_in[16];
    const float* cu  = (const float*)d_in[17];
    const float* cub = (const float*)d_in[18];
    const float* cb  = (const float*)d_in[19];
    const float* cbb = (const float*)d_in[20];
    const float* ct  = (const float*)d_in[21];
    const float* ctb = (const float*)d_in[22];
    const float* cd  = (const float*)d_in[23];
    const float* cdb = (const float*)d_in[24];
    const float* dW  = (const float*)d_in[25];
    const float* dfb = (const float*)d_in[26];
    float* out = (float*)d_out;

    wtrans_kernel<<<750, 256>>>(cu, cb, ct, cd, bowW);
    bow_kernel<<<dim3(64, 2), 256>>>(qwt, dwt, wrd, bowb);
    conv_kernel<<<dim3(1, 64), 256>>>(qwt, 20, 0, wrd, cub, cbb, ctb);
    conv_kernel<<<dim3(16, 64), 256>>>(dwt, 512, 1, wrd, cub, cbb, ctb);
    entity_kernel<<<dim3(5, 64), 256>>>(qei, qet, qew, wrd, cdb, ent, car, 5, 0);
    entity_kernel<<<dim3(10, 64), 256>>>(dei, det, dew, wrd, cdb, ent, car, 10, 1);
    zero_kernel<<<(B_*4*64*11 + 511) / 512, 512>>>();
    pool_kernel<<<dim3(8, 4, 64), 256>>>(dwm, dem);
    finalize_kernel<<<64, 256>>>(qwm, qem, dW, dfb, out);
}

// round 3
// speedup vs baseline: 1.0011x; 1.0011x over previous
#include <cuda_runtime.h>
#include <math.h>

#define B_    64
#define LQ_   20
#define LD_   512
#define D_    300

// ---------------- constants ----------------
__constant__ float c_mu[11] = {1.0f,0.9f,0.7f,0.5f,0.3f,0.1f,-0.1f,-0.3f,-0.5f,-0.7f,-0.9f};
// c2 = -0.5 / sigma^2
__constant__ float c_c2[11] = {-500000.0f,-50.f,-50.f,-50.f,-50.f,-50.f,-50.f,-50.f,-50.f,-50.f,-50.f};
__constant__ int c_poolQ[16] = {0,0,0,1,2,1,1,2,2,3,3,3,0,1,2,3};
__constant__ int c_poolD[16] = {0,2,1,0,0,1,2,1,2,0,1,2,3,3,3,3};
__constant__ int c_qbase[4]  = {0,20,39,57};
__constant__ int c_qlen[4]   = {20,19,18,5};
__constant__ int c_dlen[4]   = {512,511,510,10};

// ---------------- device scratch ----------------
// q vectors: rows 0..19 qu, 20..38 qb, 39..56 qt, 57..61 qs, 62..63 zero
__device__ float g_qall[(size_t)B_*64*128];
// d vectors: [b][dtype 0..3][pos<512][128]; 0=du(512),1=db(511),2=dt(510),3=ds(10)
__device__ float g_dall[(size_t)B_*4*512*128];
// gaussian accumulators: [b][dtype][qrow 64][11]
__device__ float g_acc[(size_t)B_*4*64*11];
__device__ float g_qbow[B_*128];
__device__ float g_dbow[B_*128];
// transposed weights: Wt[(kk*300+dd)*128 + o]
__device__ float g_WtU[300*128];
__device__ float g_WtB[600*128];
__device__ float g_WtT[900*128];
__device__ float g_WtD[1500*128];
__device__ float g_bowT[300*128];

// ---------------- weight transpose ----------------
__global__ void wtrans_kernel(const float* __restrict__ cu, const float* __restrict__ cb,
                              const float* __restrict__ ct, const float* __restrict__ cd,
                              const float* __restrict__ bw)
{
    int idx = blockIdx.x*blockDim.x + threadIdx.x;
    if (idx >= 1500*128) return;
    int o = idx & 127, kd = idx >> 7;
    g_WtD[idx] = cd[o*1500 + kd];
    if (kd < 300) { g_WtU[idx] = cu[o*300 + kd]; g_bowT[idx] = bw[o*300 + kd]; }
    if (kd < 600) { g_WtB[idx] = cb[o*600 + kd]; }
    if (kd < 900) { g_WtT[idx] = ct[o*900 + kd]; }
}

// ---------------- zero accumulators ----------------
__global__ void zero_kernel()
{
    int idx = blockIdx.x*blockDim.x + threadIdx.x;
    if (idx < B_*4*64*11) g_acc[idx] = 0.f;
}

// ---------------- bow: w_bow[b][o] = (sum_l emb[tok_l]) . bowW_o + L*bow_b[o] ----------------
__global__ void bow_kernel(const int* __restrict__ qwt, const int* __restrict__ dwt,
                           const float* __restrict__ emb, const float* __restrict__ bow_b)
{
    int b = blockIdx.x; int side = blockIdx.y;
    const int* tok = side ? (dwt + b*LD_) : (qwt + b*LQ_);
    int L = side ? LD_ : LQ_;
    __shared__ float sv[304];
    for (int idx = threadIdx.x; idx < 300; idx += blockDim.x) {
        float s = 0.f;
        #pragma unroll 4
        for (int l = 0; l < L; l++) s += emb[(size_t)tok[l]*300 + idx];
        sv[idx] = s;
    }
    __syncthreads();
    int t = threadIdx.x;
    if (t < 128) {
        float acc = (float)L * bow_b[t];
        #pragma unroll 4
        for (int dd = 0; dd < 300; dd++) acc = fmaf(sv[dd], g_bowT[dd*128 + t], acc);
        (side ? g_dbow : g_qbow)[b*128 + t] = acc;
    }
}

// ---------------- fused uni/bi/tri conv + relu + L2 norm ----------------
__device__ __forceinline__ void conv_store_type(float* acc, float bias, float* buf, float* ninv,
                                                float* outp, int p0, int pbase, int o, int Lvalid)
{
    #pragma unroll
    for (int p = 0; p < 16; p++) {
        acc[p] = fmaxf(acc[p] + bias, 0.f);
        buf[(pbase + p)*128 + o] = acc[p];
    }
    __syncthreads();
    int wid = threadIdx.x >> 5, lane = threadIdx.x & 31;
    #pragma unroll
    for (int r = 0; r < 4; r++) {
        int p = wid*4 + r;
        float s = 0.f;
        #pragma unroll
        for (int j = 0; j < 4; j++) { float v = buf[p*128 + lane + 32*j]; s = fmaf(v, v, s); }
        #pragma unroll
        for (int off = 16; off >= 1; off >>= 1) s += __shfl_xor_sync(0xffffffffu, s, off);
        if (lane == 0) ninv[p] = 1.f / fmaxf(sqrtf(s), 1e-10f);
    }
    __syncthreads();
    #pragma unroll
    for (int p = 0; p < 16; p++) {
        int pg = p0 + pbase + p;
        if (pg < Lvalid) outp[(size_t)pg*128 + o] = acc[p] * ninv[pbase + p];
    }
    __syncthreads();
}

__global__ void __launch_bounds__(256, 2) conv_kernel(
    const int* __restrict__ tok_all, int L, int side,
    const float* __restrict__ emb,
    const float* __restrict__ bU, const float* __restrict__ bB, const float* __restrict__ bT)
{
    __shared__ float A[34*300];             // 40800 B; reused as buf/ninv later
    float* buf  = A;                        // [32][128]
    float* ninv = A + 32*128;               // [32]

    int b = blockIdx.y, chunk = blockIdx.x;
    int p0 = chunk*32;
    const int* tok = tok_all + b*L;
    int nrows = L - p0; if (nrows > 34) nrows = 34;
    for (int idx = threadIdx.x; idx < 34*300; idx += 256) {
        int r = idx / 300;
        A[idx] = (r < nrows) ? emb[(size_t)tok[p0 + r]*300 + (idx - r*300)] : 0.f;
    }
    __syncthreads();

    int o = threadIdx.x & 127;
    int half = threadIdx.x >> 7;
    int pbase = half*16;
    float accU[16], accB[16], accT[16];
    #pragma unroll
    for (int p = 0; p < 16; p++) { accU[p]=0.f; accB[p]=0.f; accT[p]=0.f; }

    const float* Arow = A + pbase*300;
    for (int dd = 0; dd < 300; dd += 2) {
        float2 a2[18];
        #pragma unroll
        for (int j = 0; j < 18; j++) a2[j] = *(const float2*)(Arow + j*300 + dd);
        float wu0  = g_WtU[dd*128+o],         wu1  = g_WtU[(dd+1)*128+o];
        float wb00 = g_WtB[dd*128+o],         wb01 = g_WtB[(dd+1)*128+o];
        float wb10 = g_WtB[(300+dd)*128+o],   wb11 = g_WtB[(301+dd)*128+o];
        float wt00 = g_WtT[dd*128+o],         wt01 = g_WtT[(dd+1)*128+o];
        float wt10 = g_WtT[(300+dd)*128+o],   wt11 = g_WtT[(301+dd)*128+o];
        float wt20 = g_WtT[(600+dd)*128+o],   wt21 = g_WtT[(601+dd)*128+o];
        #pragma unroll
        for (int p = 0; p < 16; p++) {
            accU[p] = fmaf(a2[p].x,   wu0,  accU[p]);
            accU[p] = fmaf(a2[p].y,   wu1,  accU[p]);
            accB[p] = fmaf(a2[p].x,   wb00, accB[p]);
            accB[p] = fmaf(a2[p].y,   wb01, accB[p]);
            accB[p] = fmaf(a2[p+1].x, wb10, accB[p]);
            accB[p] = fmaf(a2[p+1].y, wb11, accB[p]);
            accT[p] = fmaf(a2[p].x,   wt00, accT[p]);
            accT[p] = fmaf(a2[p].y,   wt01, accT[p]);
            accT[p] = fmaf(a2[p+1].x, wt10, accT[p]);
            accT[p] = fmaf(a2[p+1].y, wt11, accT[p]);
            accT[p] = fmaf(a2[p+2].x, wt20, accT[p]);
            accT[p] = fmaf(a2[p+2].y, wt21, accT[p]);
        }
    }
    __syncthreads();   // last A read done; A reused as buf below

    float *oU, *oB, *oT; int Lu, Lb2, Lt2;
    if (side == 0) {
        float* qb_ = g_qall + (size_t)b*64*128;
        oU = qb_; oB = qb_ + 20*128; oT = qb_ + 39*128;
        Lu = 20; Lb2 = 19; Lt2 = 18;
    } else {
        float* dbp = g_dall + (size_t)b*4*512*128;
        oU = dbp; oB = dbp + (size_t)512*128; oT = dbp + (size_t)2*512*128;
        Lu = 512; Lb2 = 511; Lt2 = 510;
    }
    conv_store_type(accU, bU[o], buf, ninv, oU, p0, pbase, o, Lu);
    conv_store_type(accB, bB[o], buf, ninv, oB, p0, pbase, o, Lb2);
    conv_store_type(accT, bT[o], buf, ninv, oT, p0, pbase, o, Lt2);
}

// ---------------- entity branch: desc conv + attention + L2 ----------------
__global__ void __launch_bounds__(256, 2) entity_kernel(
    const int* __restrict__ ids_e, const int* __restrict__ ids_desc, const int* __restrict__ ids_car,
    const float* __restrict__ emb, const float* __restrict__ bD,
    const float* __restrict__ ent_emb, const float* __restrict__ car_emb,
    int NE, int side)
{
    __shared__ float A[20*300];
    __shared__ float econv[128];
    __shared__ float att[10];
    __shared__ float sc[10];
    __shared__ float part[8];
    __shared__ float wbs[128];
    __shared__ int   cid[10];
    __shared__ float sninv;

    int b = blockIdx.y, e = blockIdx.x;
    int t = threadIdx.x;
    const float* bow = side ? (g_dbow + b*128) : (g_qbow + b*128);
    const int* dtok = ids_desc + (b*NE + e)*20;
    for (int idx = t; idx < 20*300; idx += 256) {
        int r = idx / 300;
        A[idx] = emb[(size_t)dtok[r]*300 + (idx - r*300)];
    }
    if (t < 128) wbs[t] = bow[t];
    if (t < 10)  cid[t] = ids_car[(b*NE + e)*10 + t];
    __syncthreads();

    // desc conv (window 5, 16 positions, 128 filters), max over positions
    int o = t & 127, half = t >> 7;
    float acc[8];
    #pragma unroll
    for (int p = 0; p < 8; p++) acc[p] = 0.f;
    const float* Arow = A + half*8*300;
    for (int dd = 0; dd < 300; dd += 2) {
        float2 a2[12];
        #pragma unroll
        for (int j = 0; j < 12; j++) a2[j] = *(const float2*)(Arow + j*300 + dd);
        #pragma unroll
        for (int kk = 0; kk < 5; kk++) {
            float w0 = g_WtD[(kk*300 + dd)*128 + o];
            float w1 = g_WtD[(kk*300 + dd + 1)*128 + o];
            #pragma unroll
            for (int p = 0; p < 8; p++) {
                acc[p] = fmaf(a2[p + kk].x, w0, acc[p]);
                acc[p] = fmaf(a2[p + kk].y, w1, acc[p]);
            }
        }
    }
    float bias = bD[o];
    float m = 0.f;
    #pragma unroll
    for (int p = 0; p < 8; p++) m = fmaxf(m, fmaxf(acc[p] + bias, 0.f));
    if (half == 0) econv[o] = m;
    __syncthreads();
    if (half == 1) econv[o] = fmaxf(econv[o], m);
    __syncthreads();

    // attention scores: sc[c] = dot(w_bow, car_emb[cid[c]])
    for (int c = 0; c < 10; c++) {
        float v = (t < 128) ? wbs[t] * car_emb[(size_t)cid[c]*128 + t] : 0.f;
        #pragma unroll
        for (int off = 16; off >= 1; off >>= 1) v += __shfl_xor_sync(0xffffffffu, v, off);
        if ((t & 31) == 0) part[t >> 5] = v;
        __syncthreads();
        if (t == 0) sc[c] = part[0] + part[1] + part[2] + part[3];
        __syncthreads();
    }
    if (t == 0) {
        float mx = sc[0];
        #pragma unroll
        for (int c = 1; c < 10; c++) mx = fmaxf(mx, sc[c]);
        float s = 0.f;
        float ev[10];
        #pragma unroll
        for (int c = 0; c < 10; c++) { ev[c] = __expf(sc[c] - mx); s += ev[c]; }
        float inv = 1.f / s;
        #pragma unroll
        for (int c = 0; c < 10; c++) att[c] = ev[c] * inv;
    }
    __syncthreads();

    // combine + L2 norm
    float val = 0.f, v2 = 0.f;
    if (t < 128) {
        float ewt = 0.f;
        #pragma unroll
        for (int c = 0; c < 10; c++) ewt = fmaf(att[c], car_emb[(size_t)cid[c]*128 + t], ewt);
        int eid = ids_e[b*NE + e];
        val = ent_emb[(size_t)eid*128 + t] + econv[t] + ewt;
        v2 = val * val;
    }
    #pragma unroll
    for (int off = 16; off >= 1; off >>= 1) v2 += __shfl_xor_sync(0xffffffffu, v2, off);
    if ((t & 31) == 0) part[t >> 5] = v2;
    __syncthreads();
    if (t == 0) sninv = 1.f / fmaxf(sqrtf(part[0] + part[1] + part[2] + part[3]), 1e-10f);
    __syncthreads();
    if (t < 128) {
        float* outp = (side == 0)
            ? (g_qall + ((size_t)b*64 + 57 + e)*128)
            : (g_dall + (((size_t)b*4 + 3)*512 + e)*128);
        outp[t] = val * sninv;
    }
}

// ---------------- kernel pooling ----------------
__global__ void __launch_bounds__(256) pool_kernel(const float* __restrict__ dwm,
                                                   const float* __restrict__ dem)
{
    int b = blockIdx.z, dt = blockIdx.y, chunk = blockIdx.x;
    int Ld = c_dlen[dt];
    int d0 = chunk*64;
    if (d0 >= Ld) return;

    __shared__ float sQ[64*17];
    __shared__ float sD[64*17];
    __shared__ float sMd[64];

    int tid = threadIdx.x;
    if (tid < 64) {
        int dpos = d0 + tid;
        float m = 0.f;
        if (dpos < Ld) m = (dt < 3) ? dwm[b*512 + dpos] : dem[b*10 + dpos];
        sMd[tid] = m;
    }

    int ty = tid >> 4, tx = tid & 15;
    float sim[16];
    #pragma unroll
    for (int i = 0; i < 16; i++) sim[i] = 0.f;

    int qr = tid >> 2, c4 = (tid & 3) << 2;
    for (int kk = 0; kk < 128; kk += 16) {
        __syncthreads();
        float4 vq = *(const float4*)(g_qall + ((size_t)b*64 + qr)*128 + kk + c4);
        sQ[qr*17 + c4 + 0] = vq.x; sQ[qr*17 + c4 + 1] = vq.y;
        sQ[qr*17 + c4 + 2] = vq.z; sQ[qr*17 + c4 + 3] = vq.w;
        float4 vd = *(const float4*)(g_dall + (((size_t)b*4 + dt)*512 + d0 + qr)*128 + kk + c4);
        sD[qr*17 + c4 + 0] = vd.x; sD[qr*17 + c4 + 1] = vd.y;
        sD[qr*17 + c4 + 2] = vd.z; sD[qr*17 + c4 + 3] = vd.w;
        __syncthreads();
        #pragma unroll
        for (int kkl = 0; kkl < 16; kkl++) {
            float aq[4], ad[4];
            #pragma unroll
            for (int i = 0; i < 4; i++) aq[i] = sQ[(ty*4 + i)*17 + kkl];
            #pragma unroll
            for (int j = 0; j < 4; j++) ad[j] = sD[(tx*4 + j)*17 + kkl];
            #pragma unroll
            for (int i = 0; i < 4; i++)
                #pragma unroll
                for (int j = 0; j < 4; j++)
                    sim[i*4 + j] = fmaf(aq[i], ad[j], sim[i*4 + j]);
        }
    }

    float mdv[4];
    #pragma unroll
    for (int j = 0; j < 4; j++) mdv[j] = sMd[tx*4 + j];

    float acc[44];
    #pragma unroll
    for (int i = 0; i < 44; i++) acc[i] = 0.f;
    #pragma unroll
    for (int i = 0; i < 4; i++) {
        #pragma unroll
        for (int j = 0; j < 4; j++) {
            float s = sim[i*4 + j];
            float md = mdv[j];
            #pragma unroll
            for (int k = 0; k < 11; k++) {
                float tdev = s - c_mu[k];
                float e = __expf(c_c2[k] * tdev * tdev);
                acc[i*11 + k] = fmaf(e, md, acc[i*11 + k]);
            }
        }
    }

    #pragma unroll
    for (int off = 8; off >= 1; off >>= 1)
        #pragma unroll
        for (int i = 0; i < 44; i++)
            acc[i] += __shfl_xor_sync(0xffffffffu, acc[i], off);

    if (tx == 0) {
        #pragma unroll
        for (int i = 0; i < 4; i++) {
            int qrow = ty*4 + i;
            float* dst = g_acc + (((size_t)b*4 + dt)*64 + qrow)*11;
            #pragma unroll
            for (int k = 0; k < 11; k++) atomicAdd(&dst[k], acc[i*11 + k]);
        }
    }
}

// ---------------- finalize: log/mask/dense/tanh ----------------
__global__ void finalize_kernel(const float* __restrict__ qwm, const float* __restrict__ qem,
                                const float* __restrict__ dW, const float* __restrict__ dfb,
                                float* __restrict__ out)
{
    int b = blockIdx.x, t = threadIdx.x;
    __shared__ float red[256];
    float val = 0.f;
    if (t < 176) {
        int pool = t / 11, k = t - pool*11;
        int qt = c_poolQ[pool], dtp = c_poolD[pool];
        int base = c_qbase[qt], len = c_qlen[qt];
        float s = 0.f;
        for (int r = 0; r < len; r++) {
            float a = g_acc[(((size_t)b*4 + dtp)*64 + base + r)*11 + k];
            float mq = (qt < 3) ? qwm[b*20 + r] : qem[b*5 + r];
            s += logf(fmaxf(a, 1e-10f)) * 0.01f * mq;
        }
        val = s * dW[t];
    }
    red[t] = val;
    __syncthreads();
    for (int off = 128; off >= 1; off >>= 1) {
        if (t < off) red[t] += red[t + off];
        __syncthreads();
    }
    if (t == 0) out[b] = tanhf(red[0] + dfb[0]);
}

// ---------------- launch ----------------
extern "C" void kernel_launch(void* const* d_in, const int* in_sizes, int n_in,
                              void* d_out, int out_size)
{
    const int*   qwt = (const int*)  d_in[0];
    const float* qwm = (const float*)d_in[1];
    const int*   qei = (const int*)  d_in[2];
    const int*   qet = (const int*)  d_in[3];
    const int*   qew = (const int*)  d_in[4];
    const float* qem = (const float*)d_in[5];
    const int*   dwt = (const int*)  d_in[6];
    const float* dwm = (const float*)d_in[7];
    const int*   dei = (const int*)  d_in[8];
    const int*   det = (const int*)  d_in[9];
    const int*   dew = (const int*)  d_in[10];
    const float* dem = (const float*)d_in[11];
    const float* wrd = (const float*)d_in[12];
    const float* ent = (const float*)d_in[13];
    const float* car = (const float*)d_in[14];
    const float* bowW= (const float*)d_in[15];
    const float* bowb= (const float*)d_in[16];
    const float* cu  = (const float*)d_in[17];
    const float* cub = (const float*)d_in[18];
    const float* cb  = (const float*)d_in[19];
    const float* cbb = (const float*)d_in[20];
    const float* ct  = (const float*)d_in[21];
    const float* ctb = (const float*)d_in[22];
    const float* cd  = (const float*)d_in[23];
    const float* cdb = (const float*)d_in[24];
    const float* dW  = (const float*)d_in[25];
    const float* dfb = (const float*)d_in[26];
    float* out = (float*)d_out;

    wtrans_kernel<<<750, 256>>>(cu, cb, ct, cd, bowW);
    bow_kernel<<<dim3(64, 2), 256>>>(qwt, dwt, wrd, bowb);
    conv_kernel<<<dim3(1, 64), 256>>>(qwt, 20, 0, wrd, cub, cbb, ctb);
    conv_kernel<<<dim3(16, 64), 256>>>(dwt, 512, 1, wrd, cub, cbb, ctb);
    entity_kernel<<<dim3(5, 64), 256>>>(qei, qet, qew, wrd, cdb, ent, car, 5, 0);
    entity_kernel<<<dim3(10, 64), 256>>>(dei, det, dew, wrd, cdb, ent, car, 10, 1);
    zero_kernel<<<(B_*4*64*11 + 511) / 512, 512>>>();
    pool_kernel<<<dim3(8, 4, 64), 256>>>(dwm, dem);
    finalize_kernel<<<64, 256>>>(qwm, qem, dW, dfb, out);
}